// round 1
// baseline (speedup 1.0000x reference)
#include <cuda_runtime.h>
#include <math.h>

// ---------------- problem constants ----------------
#define BATCH 32
#define HW    1024            // 32*32 tokens per batch
#define C     512
#define GROUPS 32
#define CPG   16               // channels per group
#define M_TOT (BATCH*HW)       // 32768 rows
#define EPS   1e-6f

// ---------------- scratch (device globals; no allocation allowed) ----------------
__device__ float g_hn[(long long)M_TOT * C];
__device__ float g_q [(long long)M_TOT * C];
__device__ float g_k [(long long)M_TOT * C];
__device__ float g_v [(long long)M_TOT * C];
__device__ float g_s [(long long)BATCH * HW * HW];   // 128 MB scores
__device__ float g_o [(long long)M_TOT * C];
__device__ float g_mean[BATCH * GROUPS];
__device__ float g_rstd[BATCH * GROUPS];

// ---------------- groupnorm stats: one block per (b, g) ----------------
__global__ __launch_bounds__(256)
void gn_stats_kernel(const float* __restrict__ x,
                     float* __restrict__ mean, float* __restrict__ rstd)
{
    int bg = blockIdx.x;            // 0..1023
    int b = bg >> 5;                // /32
    int g = bg & 31;
    const float* base = x + (long long)b * HW * C + g * CPG;

    float s = 0.f, s2 = 0.f;
    // 16384 elements = HW(1024) * CPG(16)
    for (int e = threadIdx.x; e < HW * CPG; e += 256) {
        int p  = e >> 4;
        int cc = e & 15;
        float v = base[(long long)p * C + cc];
        s  += v;
        s2 += v * v;
    }
    __shared__ float sh1[256], sh2[256];
    sh1[threadIdx.x] = s; sh2[threadIdx.x] = s2;
    __syncthreads();
    for (int off = 128; off > 0; off >>= 1) {
        if (threadIdx.x < off) {
            sh1[threadIdx.x] += sh1[threadIdx.x + off];
            sh2[threadIdx.x] += sh2[threadIdx.x + off];
        }
        __syncthreads();
    }
    if (threadIdx.x == 0) {
        float m   = sh1[0] * (1.f / (HW * CPG));
        float var = sh2[0] * (1.f / (HW * CPG)) - m * m;
        mean[bg] = m;
        rstd[bg] = rsqrtf(var + EPS);
    }
}

// ---------------- groupnorm apply (vectorized float4) ----------------
__global__ __launch_bounds__(256)
void gn_apply_kernel(const float* __restrict__ x,
                     const float* __restrict__ scale, const float* __restrict__ bias,
                     const float* __restrict__ mean, const float* __restrict__ rstd,
                     float* __restrict__ hn)
{
    long long i = (long long)blockIdx.x * blockDim.x + threadIdx.x;  // float4 index
    const long long N4 = (long long)M_TOT * C / 4;
    if (i >= N4) return;
    int c4  = (int)(i & 127);          // C/4 = 128
    int c   = c4 * 4;
    long long pix = i >> 7;            // /128
    int b = (int)(pix >> 10);          // /1024
    int g = c >> 4;                    // /16 (4 consecutive channels stay in one group)
    int bg = b * GROUPS + g;
    float m = mean[bg], r = rstd[bg];

    float4 v  = reinterpret_cast<const float4*>(x)[i];
    float4 sc = reinterpret_cast<const float4*>(scale)[c4];
    float4 bi = reinterpret_cast<const float4*>(bias)[c4];
    float4 o;
    o.x = (v.x - m) * r * sc.x + bi.x;
    o.y = (v.y - m) * r * sc.y + bi.y;
    o.z = (v.z - m) * r * sc.z + bi.z;
    o.w = (v.w - m) * r * sc.w + bi.w;
    reinterpret_cast<float4*>(hn)[i] = o;
}

// ---------------- generic tiled SGEMM ----------------
// C[M,N] = scale * (A[M,K] @ B) + bias + residual
//   TRANSB=false: B is [K,N] row-major
//   TRANSB=true : B is [N,K] row-major (C[i,j] = sum_k A[i,k]*B[j,k])
// blockDim = 256, tile 128x128x8, 8x8 per thread. All dims must divide tiles.
template<bool TRANSB>
__global__ __launch_bounds__(256)
void gemm_kernel(const float* __restrict__ A, const float* __restrict__ B,
                 const float* __restrict__ bias, const float* __restrict__ residual,
                 float* __restrict__ Cout,
                 int M, int N, int K, float scale,
                 long long sA, long long sB, long long sC)
{
    constexpr int BM = 128, BN = 128, BK = 8, TM = 8, TN = 8;
    __shared__ float As[BK][BM];
    __shared__ float Bs[BK][BN];

    const int bx = blockIdx.x, by = blockIdx.y, bz = blockIdx.z;
    A    += (long long)bz * sA;
    B    += (long long)bz * sB;
    Cout += (long long)bz * sC;
    const float* res = residual ? residual + (long long)bz * sC : nullptr;

    const int tid = threadIdx.x;
    const int tn = tid & 15;        // 0..15
    const int tm = tid >> 4;        // 0..15

    float acc[TM][TN];
#pragma unroll
    for (int i = 0; i < TM; i++)
#pragma unroll
        for (int j = 0; j < TN; j++) acc[i][j] = 0.f;

    // A tile load mapping: 128 rows x 8 k -> 256 float4
    const int aRow = tid >> 1;          // 0..127
    const int aCol = (tid & 1) * 4;     // 0 or 4
    const float* Aptr = A + (long long)(by * BM + aRow) * K + aCol;

    int bRow, bCol;
    const float* Bptr;
    if (TRANSB) {
        bRow = tid >> 1; bCol = (tid & 1) * 4;
        Bptr = B + (long long)(bx * BN + bRow) * K + bCol;
    } else {
        bRow = tid >> 5; bCol = (tid & 31) * 4;
        Bptr = B + (long long)bRow * N + (bx * BN + bCol);
    }

    for (int k0 = 0; k0 < K; k0 += BK) {
        float4 av = *reinterpret_cast<const float4*>(Aptr + k0);
        As[aCol + 0][aRow] = av.x;
        As[aCol + 1][aRow] = av.y;
        As[aCol + 2][aRow] = av.z;
        As[aCol + 3][aRow] = av.w;
        if (TRANSB) {
            float4 bv = *reinterpret_cast<const float4*>(Bptr + k0);
            Bs[bCol + 0][bRow] = bv.x;
            Bs[bCol + 1][bRow] = bv.y;
            Bs[bCol + 2][bRow] = bv.z;
            Bs[bCol + 3][bRow] = bv.w;
        } else {
            float4 bv = *reinterpret_cast<const float4*>(Bptr + (long long)k0 * N);
            *reinterpret_cast<float4*>(&Bs[bRow][bCol]) = bv;
        }
        __syncthreads();

#pragma unroll
        for (int kk = 0; kk < BK; kk++) {
            float ra[TM], rb[TN];
#pragma unroll
            for (int i = 0; i < TM; i++) ra[i] = As[kk][tm * TM + i];
#pragma unroll
            for (int j = 0; j < TN; j++) rb[j] = Bs[kk][tn * TN + j];
#pragma unroll
            for (int i = 0; i < TM; i++)
#pragma unroll
                for (int j = 0; j < TN; j++)
                    acc[i][j] = fmaf(ra[i], rb[j], acc[i][j]);
        }
        __syncthreads();
    }

    const int cRow0 = by * BM + tm * TM;
    const int cCol0 = bx * BN + tn * TN;
#pragma unroll
    for (int i = 0; i < TM; i++) {
        long long base = (long long)(cRow0 + i) * N + cCol0;
#pragma unroll
        for (int j = 0; j < TN; j += 4) {
            float4 v;
            v.x = acc[i][j + 0] * scale;
            v.y = acc[i][j + 1] * scale;
            v.z = acc[i][j + 2] * scale;
            v.w = acc[i][j + 3] * scale;
            if (bias) {
                v.x += bias[cCol0 + j + 0];
                v.y += bias[cCol0 + j + 1];
                v.z += bias[cCol0 + j + 2];
                v.w += bias[cCol0 + j + 3];
            }
            if (res) {
                float4 r = *reinterpret_cast<const float4*>(res + base + j);
                v.x += r.x; v.y += r.y; v.z += r.z; v.w += r.w;
            }
            *reinterpret_cast<float4*>(Cout + base + j) = v;
        }
    }
}

// ---------------- row softmax over 1024 entries, one block per row ----------------
__global__ __launch_bounds__(256)
void softmax_kernel(float* __restrict__ S)
{
    float4* row = reinterpret_cast<float4*>(S + (long long)blockIdx.x * HW);
    const int tid = threadIdx.x;
    __shared__ float red[256];

    float4 v = row[tid];
    float m = fmaxf(fmaxf(v.x, v.y), fmaxf(v.z, v.w));
    red[tid] = m;
    __syncthreads();
    for (int off = 128; off > 0; off >>= 1) {
        if (tid < off) red[tid] = fmaxf(red[tid], red[tid + off]);
        __syncthreads();
    }
    m = red[0];
    __syncthreads();

    v.x = expf(v.x - m);
    v.y = expf(v.y - m);
    v.z = expf(v.z - m);
    v.w = expf(v.w - m);
    float s = v.x + v.y + v.z + v.w;
    red[tid] = s;
    __syncthreads();
    for (int off = 128; off > 0; off >>= 1) {
        if (tid < off) red[tid] += red[tid + off];
        __syncthreads();
    }
    float inv = 1.f / red[0];
    v.x *= inv; v.y *= inv; v.z *= inv; v.w *= inv;
    row[tid] = v;
}

// ---------------- launch ----------------
extern "C" void kernel_launch(void* const* d_in, const int* in_sizes, int n_in,
                              void* d_out, int out_size)
{
    const float* x  = (const float*)d_in[0];
    const float* ns = (const float*)d_in[1];
    const float* nb = (const float*)d_in[2];
    const float* wq = (const float*)d_in[3];
    const float* bq = (const float*)d_in[4];
    const float* wk = (const float*)d_in[5];
    const float* bk = (const float*)d_in[6];
    const float* wv = (const float*)d_in[7];
    const float* bv = (const float*)d_in[8];
    const float* wp = (const float*)d_in[9];
    const float* bp = (const float*)d_in[10];
    float* out = (float*)d_out;

    float *hn, *q, *k, *v, *s, *o, *mean, *rstd;
    cudaGetSymbolAddress((void**)&hn,   g_hn);
    cudaGetSymbolAddress((void**)&q,    g_q);
    cudaGetSymbolAddress((void**)&k,    g_k);
    cudaGetSymbolAddress((void**)&v,    g_v);
    cudaGetSymbolAddress((void**)&s,    g_s);
    cudaGetSymbolAddress((void**)&o,    g_o);
    cudaGetSymbolAddress((void**)&mean, g_mean);
    cudaGetSymbolAddress((void**)&rstd, g_rstd);

    // 1. GroupNorm
    gn_stats_kernel<<<BATCH * GROUPS, 256>>>(x, mean, rstd);
    {
        long long n4 = (long long)M_TOT * C / 4;
        int blocks = (int)((n4 + 255) / 256);
        gn_apply_kernel<<<blocks, 256>>>(x, ns, nb, mean, rstd, hn);
    }

    // 2. Q, K, V projections: [32768,512] @ [512,512] + bias
    {
        dim3 grid(C / 128, M_TOT / 128, 1);   // (4, 256)
        gemm_kernel<false><<<grid, 256>>>(hn, wq, bq, nullptr, q, M_TOT, C, C, 1.f, 0, 0, 0);
        gemm_kernel<false><<<grid, 256>>>(hn, wk, bk, nullptr, k, M_TOT, C, C, 1.f, 0, 0, 0);
        gemm_kernel<false><<<grid, 256>>>(hn, wv, bv, nullptr, v, M_TOT, C, C, 1.f, 0, 0, 0);
    }

    // 3. scores = q @ k^T * c^-0.5 (batched NT)
    {
        dim3 grid(HW / 128, HW / 128, BATCH);   // (8, 8, 32)
        float sc = 1.f / sqrtf((float)C);
        gemm_kernel<true><<<grid, 256>>>(q, k, nullptr, nullptr, s,
                                         HW, HW, C, sc,
                                         (long long)HW * C, (long long)HW * C,
                                         (long long)HW * HW);
    }

    // 4. softmax rows
    softmax_kernel<<<BATCH * HW, 256>>>(s);

    // 5. o = attn @ v (batched NN)
    {
        dim3 grid(C / 128, HW / 128, BATCH);    // (4, 8, 32)
        gemm_kernel<false><<<grid, 256>>>(s, v, nullptr, nullptr, o,
                                          HW, C, HW, 1.f,
                                          (long long)HW * HW, (long long)HW * C,
                                          (long long)HW * C);
    }

    // 6. out = o @ wp + bp + x (residual)
    {
        dim3 grid(C / 128, M_TOT / 128, 1);
        gemm_kernel<false><<<grid, 256>>>(o, wp, bp, x, out, M_TOT, C, C, 1.f, 0, 0, 0);
    }
}

// round 3
// speedup vs baseline: 7.1498x; 7.1498x over previous
#include <cuda_runtime.h>
#include <cuda_bf16.h>
#include <cstdint>
#include <math.h>

// ---------------- problem constants ----------------
#define BATCH 32
#define HW    1024
#define C     512
#define GROUPS 32
#define CPG   16
#define M_TOT (BATCH*HW)       // 32768
#define EPS   1e-6f

// ---------------- scratch ----------------
__device__ __nv_bfloat16 g_hn[(long long)M_TOT * C];
__device__ __nv_bfloat16 g_q [(long long)M_TOT * C];
__device__ __nv_bfloat16 g_k [(long long)M_TOT * C];
__device__ __nv_bfloat16 g_v [(long long)M_TOT * C];
__device__ __nv_bfloat16 g_s [(long long)BATCH * HW * HW];  // bf16 scores/probs
__device__ __nv_bfloat16 g_o [(long long)M_TOT * C];
__device__ __nv_bfloat16 g_w [4][(long long)C * C];         // bf16 weights (row-major copy)
__device__ float g_mean[BATCH * GROUPS];
__device__ float g_rstd[BATCH * GROUPS];

// ---------------- helpers ----------------
__device__ __forceinline__ uint32_t smem_u32(const void* p) {
    uint32_t a;
    asm("{ .reg .u64 t; cvta.to.shared.u64 t, %1; cvt.u32.u64 %0, t; }" : "=r"(a) : "l"(p));
    return a;
}
#define LDSM_X4(r0,r1,r2,r3,addr) \
    asm volatile("ldmatrix.sync.aligned.m8n8.x4.shared.b16 {%0,%1,%2,%3}, [%4];" \
        : "=r"(r0),"=r"(r1),"=r"(r2),"=r"(r3) : "r"(addr))
#define LDSM_X4T(r0,r1,r2,r3,addr) \
    asm volatile("ldmatrix.sync.aligned.m8n8.x4.trans.shared.b16 {%0,%1,%2,%3}, [%4];" \
        : "=r"(r0),"=r"(r1),"=r"(r2),"=r"(r3) : "r"(addr))
#define MMA_BF16(d, a, b) \
    asm volatile("mma.sync.aligned.m16n8k16.row.col.f32.bf16.bf16.f32 " \
        "{%0,%1,%2,%3}, {%4,%5,%6,%7}, {%8,%9}, {%0,%1,%2,%3};" \
        : "+f"((d)[0]), "+f"((d)[1]), "+f"((d)[2]), "+f"((d)[3]) \
        : "r"((a)[0]), "r"((a)[1]), "r"((a)[2]), "r"((a)[3]), "r"((b)[0]), "r"((b)[1]))
#define CP_ASYNC16(smem, gmem) \
    asm volatile("cp.async.cg.shared.global [%0], [%1], 16;" :: "r"(smem), "l"(gmem))
#define CP_COMMIT() asm volatile("cp.async.commit_group;" ::: "memory")
#define CP_WAIT1()  asm volatile("cp.async.wait_group 1;" ::: "memory")

// ---------------- groupnorm stats ----------------
__global__ __launch_bounds__(256)
void gn_stats_kernel(const float* __restrict__ x, float* __restrict__ mean, float* __restrict__ rstd)
{
    int bg = blockIdx.x, b = bg >> 5, g = bg & 31;
    const float* base = x + (long long)b * HW * C + g * CPG;
    float s = 0.f, s2 = 0.f;
    for (int e = threadIdx.x; e < HW * CPG; e += 256) {
        int p = e >> 4, cc = e & 15;
        float v = base[(long long)p * C + cc];
        s += v; s2 += v * v;
    }
    __shared__ float sh1[256], sh2[256];
    sh1[threadIdx.x] = s; sh2[threadIdx.x] = s2;
    __syncthreads();
    for (int off = 128; off > 0; off >>= 1) {
        if (threadIdx.x < off) { sh1[threadIdx.x] += sh1[threadIdx.x + off]; sh2[threadIdx.x] += sh2[threadIdx.x + off]; }
        __syncthreads();
    }
    if (threadIdx.x == 0) {
        float m = sh1[0] * (1.f / (HW * CPG));
        float var = sh2[0] * (1.f / (HW * CPG)) - m * m;
        mean[bg] = m; rstd[bg] = rsqrtf(var + EPS);
    }
}

// ---------------- groupnorm apply -> bf16 ----------------
__global__ __launch_bounds__(256)
void gn_apply_kernel(const float* __restrict__ x, const float* __restrict__ scale,
                     const float* __restrict__ bias, const float* __restrict__ mean,
                     const float* __restrict__ rstd, __nv_bfloat16* __restrict__ hn)
{
    long long i = (long long)blockIdx.x * blockDim.x + threadIdx.x;
    const long long N4 = (long long)M_TOT * C / 4;
    if (i >= N4) return;
    int c4 = (int)(i & 127), c = c4 * 4;
    long long pix = i >> 7;
    int b = (int)(pix >> 10);
    int bg = b * GROUPS + (c >> 4);
    float m = mean[bg], r = rstd[bg];
    float4 v = reinterpret_cast<const float4*>(x)[i];
    float4 sc = reinterpret_cast<const float4*>(scale)[c4];
    float4 bi = reinterpret_cast<const float4*>(bias)[c4];
    float o0 = (v.x - m) * r * sc.x + bi.x;
    float o1 = (v.y - m) * r * sc.y + bi.y;
    float o2 = (v.z - m) * r * sc.z + bi.z;
    float o3 = (v.w - m) * r * sc.w + bi.w;
    __nv_bfloat162* h2 = reinterpret_cast<__nv_bfloat162*>(hn) + i * 2;
    h2[0] = __floats2bfloat162_rn(o0, o1);
    h2[1] = __floats2bfloat162_rn(o2, o3);
}

// ---------------- fp32 -> bf16 copy (weights) ----------------
__global__ __launch_bounds__(256)
void cvt_bf16_kernel(const float* __restrict__ w, __nv_bfloat16* __restrict__ o, int n4)
{
    int i = blockIdx.x * 256 + threadIdx.x;
    if (i >= n4) return;
    float4 v = reinterpret_cast<const float4*>(w)[i];
    __nv_bfloat162* h2 = reinterpret_cast<__nv_bfloat162*>(o) + i * 2;
    h2[0] = __floats2bfloat162_rn(v.x, v.y);
    h2[1] = __floats2bfloat162_rn(v.z, v.w);
}

// ---------------- HMMA GEMM ----------------
// TB=false (NT): D = A[M,K] @ B[N,K]^T, both K-major.
// TB=true  (NN): D = A[M,K] @ B[K,N], B row-major (ldmatrix.trans).
// MODE 0: bf16 out (+bias, *scale).  MODE 2: fp32 out + bias + residual.
// Tiles: BM=BN=128, BK=32. 256 threads = 8 warps (4 m x 2 n), warp tile 32x64.
#define BK 32
#define A_ROWB 80u         // 40 bf16 per padded row
#define BNN_ROWB 272u      // 136 bf16 per padded row (NN B tile)
#define STAGE 20480u
#define BOFF  10240u
#define NSTG  3

template<bool TB, int MODE>
__global__ void __launch_bounds__(256, 2)
mma_gemm(const __nv_bfloat16* __restrict__ A, const __nv_bfloat16* __restrict__ B,
         const float* __restrict__ bias, const float* __restrict__ residual,
         void* __restrict__ Out, int K, int Ntot,
         float scale, long long sA, long long sB, long long sO)
{
    extern __shared__ char dyn[];
    const uint32_t smem0 = smem_u32(dyn);

    const int tid = threadIdx.x, lane = tid & 31, wid = tid >> 5;
    const int warp_m = wid & 3, warp_n = wid >> 2;
    const int bx = blockIdx.x, by = blockIdx.y, bz = blockIdx.z;

    const char* gA = (const char*)(A + bz * sA);
    const char* gB = (const char*)(B + bz * sB);

    // A-tile load mapping: 512 chunks of 16B (128 rows x 4)
    const int aRow = tid >> 1;                  // rep adds 128
    const int aCc  = (tid & 1) * 2;             // rep adds nothing; handle 2 reps differently
    // simpler: chunk c = tid + rep*256; row=c>>2, cc=c&3
    const int NC = K / BK;

    float acc[2][8][4];
#pragma unroll
    for (int mt = 0; mt < 2; mt++)
#pragma unroll
        for (int nt = 0; nt < 8; nt++)
#pragma unroll
            for (int e = 0; e < 4; e++) acc[mt][nt][e] = 0.f;

    auto load_chunk = [&](int ci) {
        const uint32_t st = smem0 + (uint32_t)(ci % NSTG) * STAGE;
#pragma unroll
        for (int rep = 0; rep < 2; rep++) {
            int c = tid + rep * 256;
            int row = c >> 2, cc = c & 3;
            uint32_t sa = st + (uint32_t)row * A_ROWB + (uint32_t)cc * 16;
            const char* ga = gA + ((long long)(by * 128 + row) * K) * 2 + (long long)ci * 64 + cc * 16;
            CP_ASYNC16(sa, ga);
        }
        if (TB) {
            // B tile [32][128] row-major (rows = k)
#pragma unroll
            for (int rep = 0; rep < 2; rep++) {
                int c = tid + rep * 256;
                int row = c >> 4, cc = c & 15;
                uint32_t sb = st + BOFF + (uint32_t)row * BNN_ROWB + (uint32_t)cc * 16;
                const char* gb = gB + ((long long)(ci * BK + row) * Ntot) * 2 + (long long)bx * 256 + cc * 16;
                CP_ASYNC16(sb, gb);
            }
        } else {
            // B tile [128][32] K-major
#pragma unroll
            for (int rep = 0; rep < 2; rep++) {
                int c = tid + rep * 256;
                int row = c >> 2, cc = c & 3;
                uint32_t sb = st + BOFF + (uint32_t)row * A_ROWB + (uint32_t)cc * 16;
                const char* gb = gB + ((long long)(bx * 128 + row) * K) * 2 + (long long)ci * 64 + cc * 16;
                CP_ASYNC16(sb, gb);
            }
        }
        CP_COMMIT();
    };

    load_chunk(0);
    load_chunk(1);

    const int lan15 = lane & 15;
    const int hi8   = (lane >> 4) << 3;     // 0 or 8

    for (int i = 0; i < NC; ++i) {
        CP_WAIT1();
        __syncthreads();
        const uint32_t smA = smem0 + (uint32_t)(i % NSTG) * STAGE;
        const uint32_t smB = smA + BOFF;
#pragma unroll
        for (int ks = 0; ks < 2; ks++) {
            uint32_t a[2][4];
#pragma unroll
            for (int mt = 0; mt < 2; mt++) {
                uint32_t ad = smA + (uint32_t)(warp_m * 32 + mt * 16 + lan15) * A_ROWB
                                  + (uint32_t)(ks * 16 + hi8) * 2;
                LDSM_X4(a[mt][0], a[mt][1], a[mt][2], a[mt][3], ad);
            }
            uint32_t b[8][2];
            if (TB) {
#pragma unroll
                for (int np = 0; np < 4; np++) {
                    uint32_t ad = smB + (uint32_t)(ks * 16 + lan15) * BNN_ROWB
                                      + (uint32_t)(warp_n * 64 + np * 16 + hi8) * 2;
                    uint32_t r0, r1, r2, r3;
                    LDSM_X4T(r0, r1, r2, r3, ad);
                    b[2*np][0] = r0; b[2*np][1] = r1;
                    b[2*np+1][0] = r2; b[2*np+1][1] = r3;
                }
            } else {
#pragma unroll
                for (int np = 0; np < 4; np++) {
                    uint32_t ad = smB + (uint32_t)(warp_n * 64 + np * 16 + lan15) * A_ROWB
                                      + (uint32_t)(ks * 16 + hi8) * 2;
                    uint32_t r0, r1, r2, r3;
                    LDSM_X4(r0, r1, r2, r3, ad);
                    b[2*np][0] = r0; b[2*np][1] = r2;
                    b[2*np+1][0] = r1; b[2*np+1][1] = r3;
                }
            }
#pragma unroll
            for (int mt = 0; mt < 2; mt++)
#pragma unroll
                for (int nt = 0; nt < 8; nt++)
                    MMA_BF16(acc[mt][nt], a[mt], b[nt]);
        }
        __syncthreads();
        int nc = i + 2;
        if (nc < NC) load_chunk(nc);
        else CP_COMMIT();   // keep group accounting uniform
    }

    // ---------------- epilogue ----------------
    const int group = lane >> 2, tig = lane & 3;
#pragma unroll
    for (int mt = 0; mt < 2; mt++) {
        const int r0 = by * 128 + warp_m * 32 + mt * 16 + group;
#pragma unroll
        for (int nt = 0; nt < 8; nt++) {
            const int cg = bx * 128 + warp_n * 64 + nt * 8 + tig * 2;
            if (MODE == 2) {
                float b0 = bias[cg], b1 = bias[cg + 1];
                {
                    long long idx = bz * sO + (long long)r0 * Ntot + cg;
                    const float2 rv = *(const float2*)(residual + idx);
                    float2 v = { acc[mt][nt][0] * scale + b0 + rv.x,
                                 acc[mt][nt][1] * scale + b1 + rv.y };
                    *(float2*)((float*)Out + idx) = v;
                }
                {
                    long long idx = bz * sO + (long long)(r0 + 8) * Ntot + cg;
                    const float2 rv = *(const float2*)(residual + idx);
                    float2 v = { acc[mt][nt][2] * scale + b0 + rv.x,
                                 acc[mt][nt][3] * scale + b1 + rv.y };
                    *(float2*)((float*)Out + idx) = v;
                }
            } else {
                float b0 = 0.f, b1 = 0.f;
                if (bias) { b0 = bias[cg]; b1 = bias[cg + 1]; }
                __nv_bfloat16* op = (__nv_bfloat16*)Out + bz * sO;
                *(__nv_bfloat162*)(op + (long long)r0 * Ntot + cg) =
                    __floats2bfloat162_rn(acc[mt][nt][0] * scale + b0, acc[mt][nt][1] * scale + b1);
                *(__nv_bfloat162*)(op + (long long)(r0 + 8) * Ntot + cg) =
                    __floats2bfloat162_rn(acc[mt][nt][2] * scale + b0, acc[mt][nt][3] * scale + b1);
            }
        }
    }
}

// ---------------- softmax on bf16 rows of 1024 ----------------
__global__ __launch_bounds__(256)
void softmax_bf16_kernel(__nv_bfloat16* __restrict__ S)
{
    __nv_bfloat162* row = reinterpret_cast<__nv_bfloat162*>(S + (long long)blockIdx.x * HW);
    const int tid = threadIdx.x;
    __shared__ float red[256];
    __nv_bfloat162 a = row[tid * 2], b = row[tid * 2 + 1];
    float2 fa = __bfloat1622float2(a), fb = __bfloat1622float2(b);
    float m = fmaxf(fmaxf(fa.x, fa.y), fmaxf(fb.x, fb.y));
    red[tid] = m; __syncthreads();
    for (int off = 128; off > 0; off >>= 1) {
        if (tid < off) red[tid] = fmaxf(red[tid], red[tid + off]);
        __syncthreads();
    }
    m = red[0]; __syncthreads();
    float e0 = expf(fa.x - m), e1 = expf(fa.y - m), e2 = expf(fb.x - m), e3 = expf(fb.y - m);
    red[tid] = e0 + e1 + e2 + e3; __syncthreads();
    for (int off = 128; off > 0; off >>= 1) {
        if (tid < off) red[tid] += red[tid + off];
        __syncthreads();
    }
    float inv = 1.f / red[0];
    row[tid * 2]     = __floats2bfloat162_rn(e0 * inv, e1 * inv);
    row[tid * 2 + 1] = __floats2bfloat162_rn(e2 * inv, e3 * inv);
}

// ---------------- launch ----------------
extern "C" void kernel_launch(void* const* d_in, const int* in_sizes, int n_in,
                              void* d_out, int out_size)
{
    const float* x  = (const float*)d_in[0];
    const float* ns = (const float*)d_in[1];
    const float* nb = (const float*)d_in[2];
    const float* wq = (const float*)d_in[3];
    const float* bq = (const float*)d_in[4];
    const float* wk = (const float*)d_in[5];
    const float* bk = (const float*)d_in[6];
    const float* wv = (const float*)d_in[7];
    const float* bv = (const float*)d_in[8];
    const float* wp = (const float*)d_in[9];
    const float* bp = (const float*)d_in[10];
    float* out = (float*)d_out;

    __nv_bfloat16 *hn, *q, *k, *v, *s, *o, *wbf;
    float *mean, *rstd;
    cudaGetSymbolAddress((void**)&hn, g_hn);
    cudaGetSymbolAddress((void**)&q,  g_q);
    cudaGetSymbolAddress((void**)&k,  g_k);
    cudaGetSymbolAddress((void**)&v,  g_v);
    cudaGetSymbolAddress((void**)&s,  g_s);
    cudaGetSymbolAddress((void**)&o,  g_o);
    cudaGetSymbolAddress((void**)&wbf, g_w);
    cudaGetSymbolAddress((void**)&mean, g_mean);
    cudaGetSymbolAddress((void**)&rstd, g_rstd);
    __nv_bfloat16* wqB = wbf;
    __nv_bfloat16* wkB = wbf + (long long)C * C;
    __nv_bfloat16* wvB = wbf + 2LL * C * C;
    __nv_bfloat16* wpB = wbf + 3LL * C * C;

    const int SMEM = NSTG * STAGE;
    cudaFuncSetAttribute(mma_gemm<true, 0>,  cudaFuncAttributeMaxDynamicSharedMemorySize, SMEM);
    cudaFuncSetAttribute(mma_gemm<false, 0>, cudaFuncAttributeMaxDynamicSharedMemorySize, SMEM);
    cudaFuncSetAttribute(mma_gemm<true, 2>,  cudaFuncAttributeMaxDynamicSharedMemorySize, SMEM);

    // weights -> bf16
    {
        int n4 = C * C / 4, blocks = (n4 + 255) / 256;
        cvt_bf16_kernel<<<blocks, 256>>>(wq, wqB, n4);
        cvt_bf16_kernel<<<blocks, 256>>>(wk, wkB, n4);
        cvt_bf16_kernel<<<blocks, 256>>>(wv, wvB, n4);
        cvt_bf16_kernel<<<blocks, 256>>>(wp, wpB, n4);
    }

    // groupnorm
    gn_stats_kernel<<<BATCH * GROUPS, 256>>>(x, mean, rstd);
    gn_apply_kernel<<<(int)(((long long)M_TOT * C / 4 + 255) / 256), 256>>>(x, ns, nb, mean, rstd, hn);

    // q, k, v projections: NN (B = w [512,512] row-major)
    {
        dim3 grid(C / 128, M_TOT / 128, 1);
        mma_gemm<true, 0><<<grid, 256, SMEM>>>(hn, wqB, bq, nullptr, q, C, C, 1.f, 0, 0, 0);
        mma_gemm<true, 0><<<grid, 256, SMEM>>>(hn, wkB, bk, nullptr, k, C, C, 1.f, 0, 0, 0);
        mma_gemm<true, 0><<<grid, 256, SMEM>>>(hn, wvB, bv, nullptr, v, C, C, 1.f, 0, 0, 0);
    }

    // scores = q @ k^T * c^-0.5 : NT
    {
        dim3 grid(HW / 128, HW / 128, BATCH);
        mma_gemm<false, 0><<<grid, 256, SMEM>>>(q, k, nullptr, nullptr, s, C, HW,
                                                1.f / sqrtf((float)C),
                                                (long long)HW * C, (long long)HW * C,
                                                (long long)HW * HW);
    }

    // softmax
    softmax_bf16_kernel<<<BATCH * HW, 256>>>(s);

    // o = attn @ v : NN (B = v [1024,512] row-major per batch)
    {
        dim3 grid(C / 128, HW / 128, BATCH);
        mma_gemm<true, 0><<<grid, 256, SMEM>>>(s, v, nullptr, nullptr, o, HW, C, 1.f,
                                               (long long)HW * HW, (long long)HW * C,
                                               (long long)HW * C);
    }

    // out = o @ wp + bp + x : NN, fp32 out
    {
        dim3 grid(C / 128, M_TOT / 128, 1);
        mma_gemm<true, 2><<<grid, 256, SMEM>>>(o, wpB, bp, x, out, C, C, 1.f, 0, 0, 0);
    }
}

// round 4
// speedup vs baseline: 8.6291x; 1.2069x over previous
#include <cuda_runtime.h>
#include <cuda_bf16.h>
#include <cstdint>
#include <math.h>

// ---------------- problem constants ----------------
#define BATCH 32
#define HW    1024
#define C     512
#define GROUPS 32
#define CPG   16
#define M_TOT (BATCH*HW)       // 32768
#define EPS   1e-6f
#define NQKV  1536

// ---------------- scratch ----------------
__device__ __nv_bfloat16 g_hn  [(long long)M_TOT * C];
__device__ __nv_bfloat16 g_qkv [(long long)M_TOT * NQKV];   // 96 MB: [row][q|k|v]
__device__ __nv_bfloat16 g_s   [(long long)BATCH * HW * HW];
__device__ __nv_bfloat16 g_o   [(long long)M_TOT * C];
__device__ __nv_bfloat16 g_wqkv[(long long)C * NQKV];       // [k][q|k|v]
__device__ __nv_bfloat16 g_wp  [(long long)C * C];
__device__ float g_bqkv[NQKV];
__device__ float g_mean[BATCH * GROUPS];
__device__ float g_rstd[BATCH * GROUPS];

// ---------------- helpers ----------------
__device__ __forceinline__ uint32_t smem_u32(const void* p) {
    uint32_t a;
    asm("{ .reg .u64 t; cvta.to.shared.u64 t, %1; cvt.u32.u64 %0, t; }" : "=r"(a) : "l"(p));
    return a;
}
#define LDSM_X4(r0,r1,r2,r3,addr) \
    asm volatile("ldmatrix.sync.aligned.m8n8.x4.shared.b16 {%0,%1,%2,%3}, [%4];" \
        : "=r"(r0),"=r"(r1),"=r"(r2),"=r"(r3) : "r"(addr))
#define LDSM_X4T(r0,r1,r2,r3,addr) \
    asm volatile("ldmatrix.sync.aligned.m8n8.x4.trans.shared.b16 {%0,%1,%2,%3}, [%4];" \
        : "=r"(r0),"=r"(r1),"=r"(r2),"=r"(r3) : "r"(addr))
#define MMA_BF16(d, a, b) \
    asm volatile("mma.sync.aligned.m16n8k16.row.col.f32.bf16.bf16.f32 " \
        "{%0,%1,%2,%3}, {%4,%5,%6,%7}, {%8,%9}, {%0,%1,%2,%3};" \
        : "+f"((d)[0]), "+f"((d)[1]), "+f"((d)[2]), "+f"((d)[3]) \
        : "r"((a)[0]), "r"((a)[1]), "r"((a)[2]), "r"((a)[3]), "r"((b)[0]), "r"((b)[1]))
#define CP_ASYNC16(smem, gmem) \
    asm volatile("cp.async.cg.shared.global [%0], [%1], 16;" :: "r"(smem), "l"(gmem))
#define CP_COMMIT() asm volatile("cp.async.commit_group;" ::: "memory")
#define CP_WAIT1()  asm volatile("cp.async.wait_group 1;" ::: "memory")

// ---------------- groupnorm stats ----------------
__global__ __launch_bounds__(256)
void gn_stats_kernel(const float* __restrict__ x, float* __restrict__ mean, float* __restrict__ rstd)
{
    int bg = blockIdx.x, b = bg >> 5, g = bg & 31;
    const float* base = x + (long long)b * HW * C + g * CPG;
    float s = 0.f, s2 = 0.f;
    for (int e = threadIdx.x; e < HW * CPG; e += 256) {
        int p = e >> 4, cc = e & 15;
        float v = base[(long long)p * C + cc];
        s += v; s2 += v * v;
    }
    __shared__ float sh1[256], sh2[256];
    sh1[threadIdx.x] = s; sh2[threadIdx.x] = s2;
    __syncthreads();
    for (int off = 128; off > 0; off >>= 1) {
        if (threadIdx.x < off) { sh1[threadIdx.x] += sh1[threadIdx.x + off]; sh2[threadIdx.x] += sh2[threadIdx.x + off]; }
        __syncthreads();
    }
    if (threadIdx.x == 0) {
        float m = sh1[0] * (1.f / (HW * CPG));
        float var = sh2[0] * (1.f / (HW * CPG)) - m * m;
        mean[bg] = m; rstd[bg] = rsqrtf(var + EPS);
    }
}

// ---------------- groupnorm apply -> bf16 ----------------
__global__ __launch_bounds__(256)
void gn_apply_kernel(const float* __restrict__ x, const float* __restrict__ scale,
                     const float* __restrict__ bias, const float* __restrict__ mean,
                     const float* __restrict__ rstd, __nv_bfloat16* __restrict__ hn)
{
    long long i = (long long)blockIdx.x * blockDim.x + threadIdx.x;
    const long long N4 = (long long)M_TOT * C / 4;
    if (i >= N4) return;
    int c4 = (int)(i & 127), c = c4 * 4;
    long long pix = i >> 7;
    int b = (int)(pix >> 10);
    int bg = b * GROUPS + (c >> 4);
    float m = mean[bg], r = rstd[bg];
    float4 v = reinterpret_cast<const float4*>(x)[i];
    float4 sc = reinterpret_cast<const float4*>(scale)[c4];
    float4 bi = reinterpret_cast<const float4*>(bias)[c4];
    __nv_bfloat162* h2 = reinterpret_cast<__nv_bfloat162*>(hn) + i * 2;
    h2[0] = __floats2bfloat162_rn((v.x - m) * r * sc.x + bi.x, (v.y - m) * r * sc.y + bi.y);
    h2[1] = __floats2bfloat162_rn((v.z - m) * r * sc.z + bi.z, (v.w - m) * r * sc.w + bi.w);
}

// ---------------- pack qkv weights -> bf16 [k][q|k|v] ----------------
__global__ __launch_bounds__(256)
void pack_qkvw_kernel(const float* __restrict__ wq, const float* __restrict__ wk,
                      const float* __restrict__ wv, __nv_bfloat16* __restrict__ o)
{
    int i = blockIdx.x * 256 + threadIdx.x;          // float4 index over [512][1536]
    const int TOT = C * NQKV / 4;
    if (i >= TOT) return;
    int row = i / (NQKV / 4);
    int col = (i % (NQKV / 4)) * 4;
    int sel = col >> 9;                              // /512
    const float* src = (sel == 0) ? wq : (sel == 1) ? wk : wv;
    float4 v = *reinterpret_cast<const float4*>(src + (long long)row * C + (col & 511));
    __nv_bfloat162* h2 = reinterpret_cast<__nv_bfloat162*>(o) + i * 2;
    h2[0] = __floats2bfloat162_rn(v.x, v.y);
    h2[1] = __floats2bfloat162_rn(v.z, v.w);
}

__global__ void pack_misc_kernel(const float* __restrict__ bq, const float* __restrict__ bk,
                                 const float* __restrict__ bv, float* __restrict__ bqkv,
                                 const float* __restrict__ wp, __nv_bfloat16* __restrict__ wpo)
{
    int i = blockIdx.x * 256 + threadIdx.x;
    if (i < NQKV) {
        int sel = i >> 9;
        const float* src = (sel == 0) ? bq : (sel == 1) ? bk : bv;
        bqkv[i] = src[i & 511];
    }
    // wp convert: C*C/4 = 65536 float4
    if (i < C * C / 4) {
        float4 v = reinterpret_cast<const float4*>(wp)[i];
        __nv_bfloat162* h2 = reinterpret_cast<__nv_bfloat162*>(wpo) + i * 2;
        h2[0] = __floats2bfloat162_rn(v.x, v.y);
        h2[1] = __floats2bfloat162_rn(v.z, v.w);
    }
}

// ---------------- HMMA GEMM ----------------
// TB=false (NT): D = A[M,K] @ B[N,K]^T (rows of B stride ldb).
// TB=true  (NN): D = A[M,K] @ B[K,N]  (rows of B stride ldb, ldmatrix.trans).
// MODE 0: bf16 out (+bias, *scale).  MODE 2: fp32 out + bias + residual.
// Tiles: BM=BN=128, BK=64, 2-stage double buffer. 8 warps (4m x 2n), warp 32x64.
#define A_STRIDE 144u
#define BNN_STRIDE 272u
#define BOFF  18432u
#define STAGE 36864u
#define NSTG  2

template<bool TB, int MODE>
__global__ void __launch_bounds__(256, 2)
mma_gemm(const __nv_bfloat16* __restrict__ A, const __nv_bfloat16* __restrict__ B,
         const float* __restrict__ bias, const float* __restrict__ residual,
         void* __restrict__ Out, int K, int lda, int ldb, int Ntot,
         float scale, long long sA, long long sB, long long sO)
{
    extern __shared__ char dyn[];
    const uint32_t smem0 = smem_u32(dyn);

    const int tid = threadIdx.x, lane = tid & 31, wid = tid >> 5;
    const int warp_m = wid & 3, warp_n = wid >> 2;
    const int bx = blockIdx.x, by = blockIdx.y, bz = blockIdx.z;

    const char* gA = (const char*)(A + bz * sA);
    const char* gB = (const char*)(B + bz * sB);

    const int NC = K >> 6;   // chunks of 64

    float acc[2][8][4];
#pragma unroll
    for (int mt = 0; mt < 2; mt++)
#pragma unroll
        for (int nt = 0; nt < 8; nt++)
#pragma unroll
            for (int e = 0; e < 4; e++) acc[mt][nt][e] = 0.f;

    auto load_chunk = [&](int ci) {
        const uint32_t st = smem0 + (uint32_t)(ci & (NSTG - 1)) * STAGE;
        // A tile: 128 rows x 64 k (128 B/row) -> 1024 x 16B
#pragma unroll
        for (int rep = 0; rep < 4; rep++) {
            int c = tid + rep * 256;
            int row = c >> 3, cc = c & 7;
            uint32_t sa = st + (uint32_t)row * A_STRIDE + (uint32_t)cc * 16;
            const char* ga = gA + ((long long)(by * 128 + row) * lda) * 2 + (long long)ci * 128 + cc * 16;
            CP_ASYNC16(sa, ga);
        }
        if (TB) {
            // B tile: 64 k-rows x 128 cols (256 B/row) -> 1024 x 16B
#pragma unroll
            for (int rep = 0; rep < 4; rep++) {
                int c = tid + rep * 256;
                int row = c >> 4, cc = c & 15;
                uint32_t sb = st + BOFF + (uint32_t)row * BNN_STRIDE + (uint32_t)cc * 16;
                const char* gb = gB + (((long long)(ci * 64 + row) * ldb) + bx * 128) * 2 + cc * 16;
                CP_ASYNC16(sb, gb);
            }
        } else {
            // B tile: 128 n-rows x 64 k
#pragma unroll
            for (int rep = 0; rep < 4; rep++) {
                int c = tid + rep * 256;
                int row = c >> 3, cc = c & 7;
                uint32_t sb = st + BOFF + (uint32_t)row * A_STRIDE + (uint32_t)cc * 16;
                const char* gb = gB + ((long long)(bx * 128 + row) * ldb) * 2 + (long long)ci * 128 + cc * 16;
                CP_ASYNC16(sb, gb);
            }
        }
        CP_COMMIT();
    };

    load_chunk(0);
    load_chunk(1);

    const int lan15 = lane & 15;
    const int hi8   = (lane >> 4) << 3;

    for (int i = 0; i < NC; ++i) {
        CP_WAIT1();
        __syncthreads();
        const uint32_t smA = smem0 + (uint32_t)(i & (NSTG - 1)) * STAGE;
        const uint32_t smB = smA + BOFF;
#pragma unroll
        for (int ks = 0; ks < 4; ks++) {
            uint32_t a[2][4];
#pragma unroll
            for (int mt = 0; mt < 2; mt++) {
                uint32_t ad = smA + (uint32_t)(warp_m * 32 + mt * 16 + lan15) * A_STRIDE
                                  + (uint32_t)(ks * 16 + hi8) * 2;
                LDSM_X4(a[mt][0], a[mt][1], a[mt][2], a[mt][3], ad);
            }
            uint32_t b[8][2];
            if (TB) {
#pragma unroll
                for (int np = 0; np < 4; np++) {
                    uint32_t ad = smB + (uint32_t)(ks * 16 + lan15) * BNN_STRIDE
                                      + (uint32_t)(warp_n * 64 + np * 16 + hi8) * 2;
                    uint32_t r0, r1, r2, r3;
                    LDSM_X4T(r0, r1, r2, r3, ad);
                    b[2*np][0] = r0; b[2*np][1] = r1;
                    b[2*np+1][0] = r2; b[2*np+1][1] = r3;
                }
            } else {
#pragma unroll
                for (int np = 0; np < 4; np++) {
                    uint32_t ad = smB + (uint32_t)(warp_n * 64 + np * 16 + lan15) * A_STRIDE
                                      + (uint32_t)(ks * 16 + hi8) * 2;
                    uint32_t r0, r1, r2, r3;
                    LDSM_X4(r0, r1, r2, r3, ad);
                    b[2*np][0] = r0; b[2*np][1] = r2;
                    b[2*np+1][0] = r1; b[2*np+1][1] = r3;
                }
            }
#pragma unroll
            for (int mt = 0; mt < 2; mt++)
#pragma unroll
                for (int nt = 0; nt < 8; nt++)
                    MMA_BF16(acc[mt][nt], a[mt], b[nt]);
        }
        __syncthreads();
        int nc = i + 2;
        if (nc < NC) load_chunk(nc);
        else CP_COMMIT();
    }

    // ---------------- epilogue ----------------
    const int group = lane >> 2, tig = lane & 3;
#pragma unroll
    for (int mt = 0; mt < 2; mt++) {
        const int r0 = by * 128 + warp_m * 32 + mt * 16 + group;
#pragma unroll
        for (int nt = 0; nt < 8; nt++) {
            const int cg = bx * 128 + warp_n * 64 + nt * 8 + tig * 2;
            if (MODE == 2) {
                float b0 = bias[cg], b1 = bias[cg + 1];
                {
                    long long idx = bz * sO + (long long)r0 * Ntot + cg;
                    const float2 rv = *(const float2*)(residual + idx);
                    float2 v = { acc[mt][nt][0] * scale + b0 + rv.x,
                                 acc[mt][nt][1] * scale + b1 + rv.y };
                    *(float2*)((float*)Out + idx) = v;
                }
                {
                    long long idx = bz * sO + (long long)(r0 + 8) * Ntot + cg;
                    const float2 rv = *(const float2*)(residual + idx);
                    float2 v = { acc[mt][nt][2] * scale + b0 + rv.x,
                                 acc[mt][nt][3] * scale + b1 + rv.y };
                    *(float2*)((float*)Out + idx) = v;
                }
            } else {
                float b0 = 0.f, b1 = 0.f;
                if (bias) { b0 = bias[cg]; b1 = bias[cg + 1]; }
                __nv_bfloat16* op = (__nv_bfloat16*)Out + bz * sO;
                *(__nv_bfloat162*)(op + (long long)r0 * Ntot + cg) =
                    __floats2bfloat162_rn(acc[mt][nt][0] * scale + b0, acc[mt][nt][1] * scale + b1);
                *(__nv_bfloat162*)(op + (long long)(r0 + 8) * Ntot + cg) =
                    __floats2bfloat162_rn(acc[mt][nt][2] * scale + b0, acc[mt][nt][3] * scale + b1);
            }
        }
    }
}

// ---------------- softmax: one warp per row of 1024 bf16 ----------------
__global__ __launch_bounds__(256)
void softmax_kernel(__nv_bfloat16* __restrict__ S)
{
    const int row = blockIdx.x * 8 + (threadIdx.x >> 5);
    const int lane = threadIdx.x & 31;
    uint4* p = reinterpret_cast<uint4*>(S + (long long)row * HW);

    uint4 d[4];
    float f[32];
#pragma unroll
    for (int j = 0; j < 4; j++) d[j] = p[j * 32 + lane];
#pragma unroll
    for (int j = 0; j < 4; j++) {
        const __nv_bfloat162* h = reinterpret_cast<const __nv_bfloat162*>(&d[j]);
#pragma unroll
        for (int e = 0; e < 4; e++) {
            float2 t = __bfloat1622float2(h[e]);
            f[j * 8 + e * 2]     = t.x;
            f[j * 8 + e * 2 + 1] = t.y;
        }
    }
    float m = f[0];
#pragma unroll
    for (int e = 1; e < 32; e++) m = fmaxf(m, f[e]);
#pragma unroll
    for (int off = 16; off > 0; off >>= 1)
        m = fmaxf(m, __shfl_xor_sync(0xffffffffu, m, off));
    float s = 0.f;
#pragma unroll
    for (int e = 0; e < 32; e++) { f[e] = __expf(f[e] - m); s += f[e]; }
#pragma unroll
    for (int off = 16; off > 0; off >>= 1)
        s += __shfl_xor_sync(0xffffffffu, s, off);
    float inv = 1.f / s;
#pragma unroll
    for (int j = 0; j < 4; j++) {
        __nv_bfloat162* h = reinterpret_cast<__nv_bfloat162*>(&d[j]);
#pragma unroll
        for (int e = 0; e < 4; e++)
            h[e] = __floats2bfloat162_rn(f[j * 8 + e * 2] * inv, f[j * 8 + e * 2 + 1] * inv);
        p[j * 32 + lane] = d[j];
    }
}

// ---------------- launch ----------------
extern "C" void kernel_launch(void* const* d_in, const int* in_sizes, int n_in,
                              void* d_out, int out_size)
{
    const float* x  = (const float*)d_in[0];
    const float* ns = (const float*)d_in[1];
    const float* nb = (const float*)d_in[2];
    const float* wq = (const float*)d_in[3];
    const float* bq = (const float*)d_in[4];
    const float* wk = (const float*)d_in[5];
    const float* bk = (const float*)d_in[6];
    const float* wv = (const float*)d_in[7];
    const float* bv = (const float*)d_in[8];
    const float* wp = (const float*)d_in[9];
    const float* bp = (const float*)d_in[10];
    float* out = (float*)d_out;

    __nv_bfloat16 *hn, *qkv, *s, *o, *wqkvB, *wpB;
    float *mean, *rstd, *bqkv;
    cudaGetSymbolAddress((void**)&hn,   g_hn);
    cudaGetSymbolAddress((void**)&qkv,  g_qkv);
    cudaGetSymbolAddress((void**)&s,    g_s);
    cudaGetSymbolAddress((void**)&o,    g_o);
    cudaGetSymbolAddress((void**)&wqkvB, g_wqkv);
    cudaGetSymbolAddress((void**)&wpB,  g_wp);
    cudaGetSymbolAddress((void**)&bqkv, g_bqkv);
    cudaGetSymbolAddress((void**)&mean, g_mean);
    cudaGetSymbolAddress((void**)&rstd, g_rstd);

    const int SMEM = NSTG * STAGE;   // 73728
    cudaFuncSetAttribute(mma_gemm<true, 0>,  cudaFuncAttributeMaxDynamicSharedMemorySize, SMEM);
    cudaFuncSetAttribute(mma_gemm<false, 0>, cudaFuncAttributeMaxDynamicSharedMemorySize, SMEM);
    cudaFuncSetAttribute(mma_gemm<true, 2>,  cudaFuncAttributeMaxDynamicSharedMemorySize, SMEM);

    // pack weights / biases
    pack_qkvw_kernel<<<(C * NQKV / 4 + 255) / 256, 256>>>(wq, wk, wv, wqkvB);
    pack_misc_kernel<<<(C * C / 4 + 255) / 256, 256>>>(bq, bk, bv, bqkv, wp, wpB);

    // groupnorm
    gn_stats_kernel<<<BATCH * GROUPS, 256>>>(x, mean, rstd);
    gn_apply_kernel<<<(int)(((long long)M_TOT * C / 4 + 255) / 256), 256>>>(x, ns, nb, mean, rstd, hn);

    // fused qkv projection: [32768,512] @ [512,1536]
    {
        dim3 grid(NQKV / 128, M_TOT / 128, 1);
        mma_gemm<true, 0><<<grid, 256, SMEM>>>(hn, wqkvB, bqkv, nullptr, qkv,
                                               C, C, NQKV, NQKV, 1.f, 0, 0, 0);
    }

    const __nv_bfloat16* q = qkv;
    const __nv_bfloat16* k = qkv + 512;
    const __nv_bfloat16* v = qkv + 1024;
    const long long sQKV = (long long)HW * NQKV;

    // scores = q @ k^T * c^-0.5 : NT
    {
        dim3 grid(HW / 128, HW / 128, BATCH);
        mma_gemm<false, 0><<<grid, 256, SMEM>>>(q, k, nullptr, nullptr, s,
                                                C, NQKV, NQKV, HW, 1.f / sqrtf((float)C),
                                                sQKV, sQKV, (long long)HW * HW);
    }

    // softmax (warp per row)
    softmax_kernel<<<BATCH * HW / 8, 256>>>(s);

    // o = attn @ v : NN
    {
        dim3 grid(C / 128, HW / 128, BATCH);
        mma_gemm<true, 0><<<grid, 256, SMEM>>>(s, v, nullptr, nullptr, o,
                                               HW, HW, NQKV, C, 1.f,
                                               (long long)HW * HW, sQKV, (long long)HW * C);
    }

    // out = o @ wp + bp + x : NN, fp32 out
    {
        dim3 grid(C / 128, M_TOT / 128, 1);
        mma_gemm<true, 2><<<grid, 256, SMEM>>>(o, wpB, bp, x, out,
                                               C, C, C, C, 1.f, 0, 0, 0);
    }
}